// round 9
// baseline (speedup 1.0000x reference)
#include <cuda_runtime.h>
#include <cuda_fp16.h>
#include <cstdint>

#define EPSF 1e-8f

static constexpr int IN  = 256;
static constexpr int OUT = 256;
static constexpr int G   = 5;
static constexpr int K   = IN * G;    // 1280
static constexpr int BQ  = 32768;

// GEMM tiling
static constexpr int BM = 128;
static constexpr int BN = 128;
static constexpr int BK = 64;         // halves per chunk = 128B rows
static constexpr int NCH = K / BK;    // 20
static constexpr int STAGES = 3;
static constexpr int STG_BYTES = (BM + BN) * 128;   // 32KB per stage

// K-permutation: k' = q*256 + l*8 + e, original k = 40l + r, r = 8q + e.
// Basis lane l emits 40 halves; its q-th uint4 lands at uint4 index q*32+l
// of the row -> coalesced warp stores. W uses the same permutation.

// ---------------- device globals (scratch; no allocations allowed) ----------
__device__ unsigned int g_min_u;
__device__ unsigned int g_max_u;
__device__ __half g_W[OUT * K];              // coef*scale fp16, permuted k
__device__ __half g_A[(size_t)BQ * K];       // basis fp16, permuted k

__device__ __forceinline__ unsigned int f2ord(float f) {
    unsigned int u = __float_as_uint(f);
    return (u & 0x80000000u) ? ~u : (u | 0x80000000u);
}
__device__ __forceinline__ float ord2f(unsigned int u) {
    unsigned int b = (u & 0x80000000u) ? (u & 0x7FFFFFFFu) : ~u;
    return __uint_as_float(b);
}

__device__ __forceinline__ void cp_async16(void* smem_dst, const void* gsrc) {
    uint32_t s = (uint32_t)__cvta_generic_to_shared(smem_dst);
    asm volatile("cp.async.cg.shared.global [%0], [%1], 16;\n"
                 :: "r"(s), "l"(gsrc));
}
#define CP_COMMIT() asm volatile("cp.async.commit_group;\n" ::: "memory")
#define CP_WAIT(n)  asm volatile("cp.async.wait_group %0;\n" :: "n"(n) : "memory")

// XOR swizzle for 128-byte rows, conflict-free ldmatrix
__device__ __forceinline__ uint32_t swz(uint32_t b) {
    return b ^ ((b >> 3) & 0x70);
}

__device__ __forceinline__ void ldm_x4(uint32_t* r, uint32_t addr) {
    asm volatile(
        "ldmatrix.sync.aligned.m8n8.x4.shared.b16 {%0,%1,%2,%3}, [%4];"
        : "=r"(r[0]), "=r"(r[1]), "=r"(r[2]), "=r"(r[3]) : "r"(addr));
}

// ---------------- kernel 0: reset reduction state ---------------------------
__global__ void init_kernel() {
    g_min_u = 0xFFFFFFFFu;
    g_max_u = 0x00000000u;
}

// ---------------- kernel 1: global min/max of x -----------------------------
__global__ void minmax_kernel(const float4* __restrict__ x4, int n4) {
    float lmin =  3.4e38f;
    float lmax = -3.4e38f;
    for (int i = blockIdx.x * blockDim.x + threadIdx.x; i < n4;
         i += gridDim.x * blockDim.x) {
        float4 v = x4[i];
        lmin = fminf(lmin, fminf(fminf(v.x, v.y), fminf(v.z, v.w)));
        lmax = fmaxf(lmax, fmaxf(fmaxf(v.x, v.y), fmaxf(v.z, v.w)));
    }
    #pragma unroll
    for (int off = 16; off > 0; off >>= 1) {
        lmin = fminf(lmin, __shfl_xor_sync(0xFFFFFFFFu, lmin, off));
        lmax = fmaxf(lmax, __shfl_xor_sync(0xFFFFFFFFu, lmax, off));
    }
    __shared__ float smin[8], smax[8];
    int warp = threadIdx.x >> 5, lane = threadIdx.x & 31;
    if (lane == 0) { smin[warp] = lmin; smax[warp] = lmax; }
    __syncthreads();
    if (warp == 0) {
        int nw = blockDim.x >> 5;
        lmin = (lane < nw) ? smin[lane] :  3.4e38f;
        lmax = (lane < nw) ? smax[lane] : -3.4e38f;
        #pragma unroll
        for (int off = 4; off > 0; off >>= 1) {
            lmin = fminf(lmin, __shfl_xor_sync(0xFFFFFFFFu, lmin, off));
            lmax = fmaxf(lmax, __shfl_xor_sync(0xFFFFFFFFu, lmax, off));
        }
        if (lane == 0) {
            atomicMin(&g_min_u, f2ord(lmin));
            atomicMax(&g_max_u, f2ord(lmax));
        }
    }
}

// ---------------- kernel 2: W = coef * scale -> fp16, permuted k ------------
__global__ void prep_kernel(const float* __restrict__ coef,
                            const float* __restrict__ scale) {
    int idx = blockIdx.x * blockDim.x + threadIdx.x;
    if (idx < OUT * K) {
        int o   = idx / K;
        int kp  = idx % K;
        int q   = kp >> 8;          // 0..4
        int rem = kp & 255;
        int l   = rem >> 3;         // 0..31
        int e   = rem & 7;
        int r   = q * 8 + e;        // 0..39
        int j   = r / G;
        int g   = r % G;
        int i   = l * 8 + j;
        g_W[idx] = __float2half(coef[o * K + i * G + g] * scale[o * IN + i]);
    }
}

// ---------------- kernel 3: basis(x) -> g_A, lean arithmetic ----------------
// warp handles one row; lane computes features 8l..8l+7 -> 40 halves;
// where(d<1, 1-d^3, 0) == max(1-d^3, 0) exactly; abs folded into modifiers;
// halves packed pairwise with __floats2half2_rn.
__global__ __launch_bounds__(256)
void basis_kernel(const float* __restrict__ x, const float* __restrict__ grid) {
    const int warp = threadIdx.x >> 5, lane = threadIdx.x & 31;
    const int row = blockIdx.x * 8 + warp;

    float gr[G];
    #pragma unroll
    for (int g = 0; g < G; ++g) gr[g] = __ldg(grid + g);

    const float xmin = ord2f(g_min_u);
    const float xmax = ord2f(g_max_u);
    const float s2 = 2.0f / (xmax - xmin + EPSF);
    const float c0 = -xmin * s2 - 1.0f;     // xn = fma(xv, s2, c0)

    const float4* xr = (const float4*)(x + (size_t)row * IN + lane * 8);
    float4 v0 = xr[0], v1 = xr[1];
    float xs[8] = {v0.x, v0.y, v0.z, v0.w, v1.x, v1.y, v1.z, v1.w};

    uint32_t hs[20];                        // 40 halves as 20 half2
    #pragma unroll
    for (int jj = 0; jj < 4; ++jj) {
        float vals[10];
        #pragma unroll
        for (int u = 0; u < 2; ++u) {
            const int j = jj * 2 + u;
            float xn = fmaf(xs[j], s2, c0);
            float bb[G];
            float bsum = EPSF;
            #pragma unroll
            for (int g = 0; g < G; ++g) {
                float s = xn - gr[g];
                float t = s * s;
                float v = fmaxf(fmaf(-t, fabsf(s), 1.0f), 0.0f);
                bb[g] = v;
                bsum += v;
            }
            float inv = 1.0f / bsum;
            #pragma unroll
            for (int g = 0; g < G; ++g) vals[u * 5 + g] = bb[g] * inv;
        }
        #pragma unroll
        for (int p = 0; p < 5; ++p) {
            __half2 h2 = __floats2half2_rn(vals[2 * p], vals[2 * p + 1]);
            hs[jj * 5 + p] = *(uint32_t*)&h2;
        }
    }
    uint4* gdst = (uint4*)(g_A + (size_t)row * K);
    #pragma unroll
    for (int q = 0; q < 5; ++q) {
        uint4 u = make_uint4(hs[4 * q], hs[4 * q + 1],
                             hs[4 * q + 2], hs[4 * q + 3]);
        gdst[q * 32 + lane] = u;
    }
}

// ---------------- kernel 4: fp16 GEMM, 256 thr, occ 2, single barrier -------
// 8 warps, warp tile 32x64: wm = (warp>>1)*32, wn = (warp&1)*64
// ldmatrix addresses: addr(ks) = addr(0) ^ (32*ks)  (cb bits 4-6, no carries)
__global__ __launch_bounds__(256, 2)
void kan_gemm_kernel(const float* __restrict__ bias, float* __restrict__ out) {
    extern __shared__ __align__(16) char smem_raw[];
    float* bias_s = (float*)smem_raw;              // 128 floats
    char* stg = smem_raw + 1024;                   // STAGES x 32KB

    const int tid = threadIdx.x;
    const int bm0 = blockIdx.y * BM;
    const int bn0 = blockIdx.x * BN;

    if (tid < BN) bias_s[tid] = bias[bn0 + tid];

    const int warp = tid >> 5, lane = tid & 31;
    const int wm = (warp >> 1) * 32;
    const int wn = (warp & 1) * 64;

    // tile-relative swizzled base offsets for ks=0 fragments
    uint32_t aoff[2], boff[4];
    #pragma unroll
    for (int mi = 0; mi < 2; ++mi) {
        int row = wm + mi * 16 + (lane & 15);
        int cb  = (lane >> 4) * 16;
        aoff[mi] = swz(row * 128 + cb);
    }
    #pragma unroll
    for (int ni = 0; ni < 4; ++ni) {
        int row = wn + ni * 16 + (lane & 7) + ((lane >> 4) << 3);
        int cb  = ((lane >> 3) & 1) << 4;
        boff[ni] = swz(row * 128 + cb);
    }

    float acc[2][8][4];
    #pragma unroll
    for (int mi = 0; mi < 2; ++mi)
        #pragma unroll
        for (int nf = 0; nf < 8; ++nf)
            #pragma unroll
            for (int q = 0; q < 4; ++q) acc[mi][nf][q] = 0.0f;

    auto load_stage = [&](int ic) {
        char* base = stg + (ic % STAGES) * STG_BYTES;
        char* ab = base;                 // A: 128 rows x 128B
        char* bb = base + BM * 128;      // B: 128 rows x 128B
        #pragma unroll
        for (int q = 0; q < 4; ++q) {
            int idx = q * 256 + tid;     // 0..1023
            int row = idx >> 3;
            int c   = idx & 7;
            uint32_t so = swz(row * 128 + c * 16);
            cp_async16(ab + so,
                       g_A + (size_t)(bm0 + row) * K + ic * BK + c * 8);
            cp_async16(bb + so,
                       g_W + (size_t)(bn0 + row) * K + ic * BK + c * 8);
        }
        CP_COMMIT();
    };

    load_stage(0);
    load_stage(1);

    for (int ic = 0; ic < NCH; ++ic) {
        if (ic == NCH - 1) { CP_WAIT(0); } else { CP_WAIT(1); }
        __syncthreads();

        const uint32_t abase = (uint32_t)__cvta_generic_to_shared(
            stg + (ic % STAGES) * STG_BYTES);
        const uint32_t bbase = abase + BM * 128;

        // kstep 0 fragments FIRST (LDSM ahead of the LDGSTS burst)
        uint32_t a[2][4], b[4][4];
        #pragma unroll
        for (int mi = 0; mi < 2; ++mi) ldm_x4(a[mi], abase + aoff[mi]);
        #pragma unroll
        for (int ni = 0; ni < 4; ++ni) ldm_x4(b[ni], bbase + boff[ni]);

        if (ic + 2 < NCH) load_stage(ic + 2);

        #pragma unroll
        for (int ks = 0; ks < 4; ++ks) {
            if (ks > 0) {
                const uint32_t kx = (uint32_t)(ks * 32);
                #pragma unroll
                for (int mi = 0; mi < 2; ++mi)
                    ldm_x4(a[mi], (abase + aoff[mi]) ^ kx);
                #pragma unroll
                for (int ni = 0; ni < 4; ++ni)
                    ldm_x4(b[ni], (bbase + boff[ni]) ^ kx);
            }
            #pragma unroll
            for (int mi = 0; mi < 2; ++mi)
                #pragma unroll
                for (int nf = 0; nf < 8; ++nf) {
                    const uint32_t b0 = b[nf >> 1][(nf & 1) * 2];
                    const uint32_t b1 = b[nf >> 1][(nf & 1) * 2 + 1];
                    asm volatile(
                        "mma.sync.aligned.m16n8k16.row.col.f32.f16.f16.f32 "
                        "{%0,%1,%2,%3}, {%4,%5,%6,%7}, {%8,%9}, {%0,%1,%2,%3};"
                        : "+f"(acc[mi][nf][0]), "+f"(acc[mi][nf][1]),
                          "+f"(acc[mi][nf][2]), "+f"(acc[mi][nf][3])
                        : "r"(a[mi][0]), "r"(a[mi][1]),
                          "r"(a[mi][2]), "r"(a[mi][3]),
                          "r"(b0), "r"(b1));
                }
        }
    }

    // epilogue: + bias, float2 stores
    #pragma unroll
    for (int mi = 0; mi < 2; ++mi) {
        int r = bm0 + wm + mi * 16 + (lane >> 2);
        #pragma unroll
        for (int nf = 0; nf < 8; ++nf) {
            int cl = wn + nf * 8 + ((lane & 3) << 1);
            int c = bn0 + cl;
            float b0 = bias_s[cl];
            float b1 = bias_s[cl + 1];
            float2 v0 = make_float2(acc[mi][nf][0] + b0, acc[mi][nf][1] + b1);
            float2 v1 = make_float2(acc[mi][nf][2] + b0, acc[mi][nf][3] + b1);
            *(float2*)(out + (size_t)r * OUT + c) = v0;
            *(float2*)(out + (size_t)(r + 8) * OUT + c) = v1;
        }
    }
}

// ---------------------------------------------------------------------------
static constexpr int GEMM_SMEM = 1024 + STAGES * STG_BYTES;   // ~97KB

extern "C" void kernel_launch(void* const* d_in, const int* in_sizes, int n_in,
                              void* d_out, int out_size) {
    const float* x     = (const float*)d_in[0];
    const float* grid  = (const float*)d_in[1];
    const float* coef  = (const float*)d_in[2];
    const float* scale = (const float*)d_in[3];
    const float* bias  = (const float*)d_in[4];
    float* out = (float*)d_out;

    const int B = in_sizes[0] / IN;

    cudaFuncSetAttribute(kan_gemm_kernel,
                         cudaFuncAttributeMaxDynamicSharedMemorySize,
                         GEMM_SMEM);

    init_kernel<<<1, 1>>>();
    minmax_kernel<<<2048, 256>>>((const float4*)x, in_sizes[0] / 4);
    prep_kernel<<<(OUT * K + 255) / 256, 256>>>(coef, scale);
    basis_kernel<<<B / 8, 256>>>(x, grid);

    dim3 g(OUT / BN, B / BM);
    kan_gemm_kernel<<<g, 256, GEMM_SMEM>>>(bias, out);
}

// round 10
// speedup vs baseline: 1.0536x; 1.0536x over previous
#include <cuda_runtime.h>
#include <cuda_fp16.h>
#include <cstdint>

#define EPSF 1e-8f

static constexpr int IN  = 256;
static constexpr int OUT = 256;
static constexpr int G   = 5;
static constexpr int K   = IN * G;    // 1280
static constexpr int BQ  = 32768;

// GEMM tiling: BM=128, BN=256(full OUT), 8 warps of 64x64
static constexpr int BM = 128;
static constexpr int BN = 256;
static constexpr int BK = 64;         // halves per chunk = 128B rows
static constexpr int NCH = K / BK;    // 20
static constexpr int STAGES = 3;
static constexpr int STG_BYTES = (BM + BN) * 128;   // 48KB per stage

// K-permutation: k' = q*256 + l*8 + e, original k = 40l + r, r = 8q + e.
// Basis lane l emits 40 halves; its q-th uint4 lands at uint4 index q*32+l
// of the row -> coalesced warp stores. W uses the same permutation.

// ---------------- device globals (scratch; no allocations allowed) ----------
__device__ unsigned int g_min_u;
__device__ unsigned int g_max_u;
__device__ __half g_W[OUT * K];              // coef*scale fp16, permuted k
__device__ __half g_A[(size_t)BQ * K];       // basis fp16, permuted k

__device__ __forceinline__ unsigned int f2ord(float f) {
    unsigned int u = __float_as_uint(f);
    return (u & 0x80000000u) ? ~u : (u | 0x80000000u);
}
__device__ __forceinline__ float ord2f(unsigned int u) {
    unsigned int b = (u & 0x80000000u) ? (u & 0x7FFFFFFFu) : ~u;
    return __uint_as_float(b);
}

__device__ __forceinline__ void cp_async16(void* smem_dst, const void* gsrc) {
    uint32_t s = (uint32_t)__cvta_generic_to_shared(smem_dst);
    asm volatile("cp.async.cg.shared.global [%0], [%1], 16;\n"
                 :: "r"(s), "l"(gsrc));
}
#define CP_COMMIT() asm volatile("cp.async.commit_group;\n" ::: "memory")
#define CP_WAIT(n)  asm volatile("cp.async.wait_group %0;\n" :: "n"(n) : "memory")

// XOR swizzle for 128-byte rows, conflict-free ldmatrix
__device__ __forceinline__ uint32_t swz(uint32_t b) {
    return b ^ ((b >> 3) & 0x70);
}

__device__ __forceinline__ void ldm_x4(uint32_t* r, uint32_t addr) {
    asm volatile(
        "ldmatrix.sync.aligned.m8n8.x4.shared.b16 {%0,%1,%2,%3}, [%4];"
        : "=r"(r[0]), "=r"(r[1]), "=r"(r[2]), "=r"(r[3]) : "r"(addr));
}

// ---------------- kernel 0: reset reduction state ---------------------------
__global__ void init_kernel() {
    g_min_u = 0xFFFFFFFFu;
    g_max_u = 0x00000000u;
}

// ---------------- kernel 1: global min/max of x -----------------------------
__global__ void minmax_kernel(const float4* __restrict__ x4, int n4) {
    float lmin =  3.4e38f;
    float lmax = -3.4e38f;
    for (int i = blockIdx.x * blockDim.x + threadIdx.x; i < n4;
         i += gridDim.x * blockDim.x) {
        float4 v = x4[i];
        lmin = fminf(lmin, fminf(fminf(v.x, v.y), fminf(v.z, v.w)));
        lmax = fmaxf(lmax, fmaxf(fmaxf(v.x, v.y), fmaxf(v.z, v.w)));
    }
    #pragma unroll
    for (int off = 16; off > 0; off >>= 1) {
        lmin = fminf(lmin, __shfl_xor_sync(0xFFFFFFFFu, lmin, off));
        lmax = fmaxf(lmax, __shfl_xor_sync(0xFFFFFFFFu, lmax, off));
    }
    __shared__ float smin[8], smax[8];
    int warp = threadIdx.x >> 5, lane = threadIdx.x & 31;
    if (lane == 0) { smin[warp] = lmin; smax[warp] = lmax; }
    __syncthreads();
    if (warp == 0) {
        int nw = blockDim.x >> 5;
        lmin = (lane < nw) ? smin[lane] :  3.4e38f;
        lmax = (lane < nw) ? smax[lane] : -3.4e38f;
        #pragma unroll
        for (int off = 4; off > 0; off >>= 1) {
            lmin = fminf(lmin, __shfl_xor_sync(0xFFFFFFFFu, lmin, off));
            lmax = fmaxf(lmax, __shfl_xor_sync(0xFFFFFFFFu, lmax, off));
        }
        if (lane == 0) {
            atomicMin(&g_min_u, f2ord(lmin));
            atomicMax(&g_max_u, f2ord(lmax));
        }
    }
}

// ---------------- kernel 2: W = coef * scale -> fp16, permuted k ------------
__global__ void prep_kernel(const float* __restrict__ coef,
                            const float* __restrict__ scale) {
    int idx = blockIdx.x * blockDim.x + threadIdx.x;
    if (idx < OUT * K) {
        int o   = idx / K;
        int kp  = idx % K;
        int q   = kp >> 8;          // 0..4
        int rem = kp & 255;
        int l   = rem >> 3;         // 0..31
        int e   = rem & 7;
        int r   = q * 8 + e;        // 0..39
        int j   = r / G;
        int g   = r % G;
        int i   = l * 8 + j;
        g_W[idx] = __float2half(coef[o * K + i * G + g] * scale[o * IN + i]);
    }
}

// ---------------- kernel 3: basis(x) -> g_A, lean arithmetic ----------------
__global__ __launch_bounds__(256)
void basis_kernel(const float* __restrict__ x, const float* __restrict__ grid) {
    const int warp = threadIdx.x >> 5, lane = threadIdx.x & 31;
    const int row = blockIdx.x * 8 + warp;

    float gr[G];
    #pragma unroll
    for (int g = 0; g < G; ++g) gr[g] = __ldg(grid + g);

    const float xmin = ord2f(g_min_u);
    const float xmax = ord2f(g_max_u);
    const float s2 = 2.0f / (xmax - xmin + EPSF);
    const float c0 = -xmin * s2 - 1.0f;     // xn = fma(xv, s2, c0)

    const float4* xr = (const float4*)(x + (size_t)row * IN + lane * 8);
    float4 v0 = xr[0], v1 = xr[1];
    float xs[8] = {v0.x, v0.y, v0.z, v0.w, v1.x, v1.y, v1.z, v1.w};

    uint32_t hs[20];                        // 40 halves as 20 half2
    #pragma unroll
    for (int jj = 0; jj < 4; ++jj) {
        float vals[10];
        #pragma unroll
        for (int u = 0; u < 2; ++u) {
            const int j = jj * 2 + u;
            float xn = fmaf(xs[j], s2, c0);
            float bb[G];
            float bsum = EPSF;
            #pragma unroll
            for (int g = 0; g < G; ++g) {
                float s = xn - gr[g];
                float t = s * s;
                float v = fmaxf(fmaf(-t, fabsf(s), 1.0f), 0.0f);
                bb[g] = v;
                bsum += v;
            }
            float inv = 1.0f / bsum;
            #pragma unroll
            for (int g = 0; g < G; ++g) vals[u * 5 + g] = bb[g] * inv;
        }
        #pragma unroll
        for (int p = 0; p < 5; ++p) {
            __half2 h2 = __floats2half2_rn(vals[2 * p], vals[2 * p + 1]);
            hs[jj * 5 + p] = *(uint32_t*)&h2;
        }
    }
    uint4* gdst = (uint4*)(g_A + (size_t)row * K);
    #pragma unroll
    for (int q = 0; q < 5; ++q) {
        uint4 u = make_uint4(hs[4 * q], hs[4 * q + 1],
                             hs[4 * q + 2], hs[4 * q + 3]);
        gdst[q * 32 + lane] = u;
    }
}

// ---------------- kernel 4: fp16 GEMM, 8 warps of 64x64, full-OUT tiles -----
// C[b][o] = sum_k A[b][k] * W[o][k] + bias[o]
// wm = (warp>>2)*64 (2 groups), wn = (warp&3)*64 (4 groups): 128x256 covered.
__global__ __launch_bounds__(256, 1)
void kan_gemm_kernel(const float* __restrict__ bias, float* __restrict__ out) {
    extern __shared__ __align__(16) char smem_raw[];
    float* bias_s = (float*)smem_raw;              // 256 floats
    char* stg = smem_raw + 1024;                   // STAGES x 48KB

    const int tid = threadIdx.x;
    const int bm0 = blockIdx.x * BM;

    if (tid < BN) bias_s[tid] = bias[tid];

    const int warp = tid >> 5, lane = tid & 31;
    const int wm = (warp >> 2) * 64;
    const int wn = (warp & 3) * 64;

    float acc[4][8][4];
    #pragma unroll
    for (int mi = 0; mi < 4; ++mi)
        #pragma unroll
        for (int nf = 0; nf < 8; ++nf)
            #pragma unroll
            for (int q = 0; q < 4; ++q) acc[mi][nf][q] = 0.0f;

    auto load_stage = [&](int ic) {
        char* base = stg + (ic % STAGES) * STG_BYTES;
        char* ab = base;                 // A: 128 rows x 128B
        char* bb = base + BM * 128;      // B: 256 rows x 128B
        #pragma unroll
        for (int q = 0; q < 4; ++q) {    // A: 1024 chunks
            int idx = q * 256 + tid;
            int row = idx >> 3;
            int c   = idx & 7;
            cp_async16(ab + swz(row * 128 + c * 16),
                       g_A + (size_t)(bm0 + row) * K + ic * BK + c * 8);
        }
        #pragma unroll
        for (int q = 0; q < 8; ++q) {    // B: 2048 chunks
            int idx = q * 256 + tid;
            int row = idx >> 3;
            int c   = idx & 7;
            cp_async16(bb + swz(row * 128 + c * 16),
                       g_W + (size_t)row * K + ic * BK + c * 8);
        }
        CP_COMMIT();
    };

    load_stage(0);
    load_stage(1);

    for (int ic = 0; ic < NCH; ++ic) {
        if (ic == NCH - 1) { CP_WAIT(0); } else { CP_WAIT(1); }
        __syncthreads();
        // single barrier per iter: the load below targets the buffer of chunk
        // ic-1, whose MMAs every warp finished before this barrier.
        if (ic + 2 < NCH) load_stage(ic + 2);

        const char* base = stg + (ic % STAGES) * STG_BYTES;
        const char* as = base;
        const char* bs = base + BM * 128;

        #pragma unroll
        for (int ks = 0; ks < 4; ++ks) {
            const int k0 = ks * 16;
            uint32_t a[4][4];
            #pragma unroll
            for (int mi = 0; mi < 4; ++mi) {
                int row = wm + mi * 16 + (lane & 15);
                int cb  = k0 * 2 + (lane >> 4) * 16;
                uint32_t addr = (uint32_t)__cvta_generic_to_shared(
                    as + swz(row * 128 + cb));
                ldm_x4(a[mi], addr);
            }
            uint32_t b[4][4];
            #pragma unroll
            for (int ni = 0; ni < 4; ++ni) {
                int row = wn + ni * 16 + (lane & 7) + ((lane >> 4) << 3);
                int cb  = k0 * 2 + (((lane >> 3) & 1) << 4);
                uint32_t addr = (uint32_t)__cvta_generic_to_shared(
                    bs + swz(row * 128 + cb));
                ldm_x4(b[ni], addr);
            }
            #pragma unroll
            for (int mi = 0; mi < 4; ++mi)
                #pragma unroll
                for (int nf = 0; nf < 8; ++nf) {
                    const uint32_t b0 = b[nf >> 1][(nf & 1) * 2];
                    const uint32_t b1 = b[nf >> 1][(nf & 1) * 2 + 1];
                    asm volatile(
                        "mma.sync.aligned.m16n8k16.row.col.f32.f16.f16.f32 "
                        "{%0,%1,%2,%3}, {%4,%5,%6,%7}, {%8,%9}, {%0,%1,%2,%3};"
                        : "+f"(acc[mi][nf][0]), "+f"(acc[mi][nf][1]),
                          "+f"(acc[mi][nf][2]), "+f"(acc[mi][nf][3])
                        : "r"(a[mi][0]), "r"(a[mi][1]),
                          "r"(a[mi][2]), "r"(a[mi][3]),
                          "r"(b0), "r"(b1));
                }
        }
    }

    // epilogue: + bias, float2 stores
    #pragma unroll
    for (int mi = 0; mi < 4; ++mi) {
        int r = bm0 + wm + mi * 16 + (lane >> 2);
        #pragma unroll
        for (int nf = 0; nf < 8; ++nf) {
            int cl = wn + nf * 8 + ((lane & 3) << 1);
            float b0 = bias_s[cl];
            float b1 = bias_s[cl + 1];
            float2 v0 = make_float2(acc[mi][nf][0] + b0, acc[mi][nf][1] + b1);
            float2 v1 = make_float2(acc[mi][nf][2] + b0, acc[mi][nf][3] + b1);
            *(float2*)(out + (size_t)r * OUT + cl) = v0;
            *(float2*)(out + (size_t)(r + 8) * OUT + cl) = v1;
        }
    }
}

// ---------------------------------------------------------------------------
static constexpr int GEMM_SMEM = 1024 + STAGES * STG_BYTES;   // ~145KB

extern "C" void kernel_launch(void* const* d_in, const int* in_sizes, int n_in,
                              void* d_out, int out_size) {
    const float* x     = (const float*)d_in[0];
    const float* grid  = (const float*)d_in[1];
    const float* coef  = (const float*)d_in[2];
    const float* scale = (const float*)d_in[3];
    const float* bias  = (const float*)d_in[4];
    float* out = (float*)d_out;

    const int B = in_sizes[0] / IN;

    cudaFuncSetAttribute(kan_gemm_kernel,
                         cudaFuncAttributeMaxDynamicSharedMemorySize,
                         GEMM_SMEM);

    init_kernel<<<1, 1>>>();
    minmax_kernel<<<2048, 256>>>((const float4*)x, in_sizes[0] / 4);
    prep_kernel<<<(OUT * K + 255) / 256, 256>>>(coef, scale);
    basis_kernel<<<B / 8, 256>>>(x, grid);

    kan_gemm_kernel<<<B / BM, 256, GEMM_SMEM>>>(bias, out);
}

// round 12
// speedup vs baseline: 1.0755x; 1.0207x over previous
#include <cuda_runtime.h>
#include <cuda_fp16.h>
#include <cstdint>

#define EPSF 1e-8f

static constexpr int IN  = 256;
static constexpr int OUT = 256;
static constexpr int G   = 5;
static constexpr int K   = IN * G;    // 1280
static constexpr int BQ  = 32768;

// GEMM tiling: BM=128, BN=256(full OUT), 8 warps of 64x64
static constexpr int BM = 128;
static constexpr int BN = 256;
static constexpr int BK = 64;         // halves per chunk = 128B rows
static constexpr int NCH = K / BK;    // 20
static constexpr int STAGES = 3;
static constexpr int STG_BYTES = (BM + BN) * 128;   // 48KB per stage

static constexpr int PREP_BLOCKS = (OUT * K) / 256;   // 1280
static constexpr int MM_BLOCKS   = 256;               // minmax partial blocks

// K-permutation: k' = q*256 + l*8 + e, original k = 40l + r, r = 8q + e.
// Basis lane l emits 40 halves; its q-th uint4 lands at uint4 index q*32+l
// of the row -> coalesced warp stores. W uses the same permutation.

// ---------------- device globals (scratch; no allocations allowed) ----------
__device__ float  g_pmin[MM_BLOCKS];
__device__ float  g_pmax[MM_BLOCKS];
__device__ __half g_W[OUT * K];              // coef*scale fp16, permuted k
__device__ __half g_A[(size_t)BQ * K];       // basis fp16, permuted k

__device__ __forceinline__ void cp_async16(void* smem_dst, const void* gsrc) {
    uint32_t s = (uint32_t)__cvta_generic_to_shared(smem_dst);
    asm volatile("cp.async.cg.shared.global [%0], [%1], 16;\n"
                 :: "r"(s), "l"(gsrc));
}
#define CP_COMMIT() asm volatile("cp.async.commit_group;\n" ::: "memory")
#define CP_WAIT(n)  asm volatile("cp.async.wait_group %0;\n" :: "n"(n) : "memory")

// XOR swizzle for 128-byte rows, conflict-free ldmatrix
__device__ __forceinline__ uint32_t swz(uint32_t b) {
    return b ^ ((b >> 3) & 0x70);
}

__device__ __forceinline__ void ldm_x4(uint32_t* r, uint32_t addr) {
    asm volatile(
        "ldmatrix.sync.aligned.m8n8.x4.shared.b16 {%0,%1,%2,%3}, [%4];"
        : "=r"(r[0]), "=r"(r[1]), "=r"(r[2]), "=r"(r[3]) : "r"(addr));
}

// ---------------- kernel 1: prep W (blocks 0..1279) + minmax partials -------
__global__ __launch_bounds__(256)
void pre_kernel(const float* __restrict__ x,
                const float* __restrict__ coef,
                const float* __restrict__ scale,
                int n4) {
    const int blk = blockIdx.x;
    const int tid = threadIdx.x;

    if (blk < PREP_BLOCKS) {
        // W = coef * scale -> fp16, permuted k
        int idx = blk * 256 + tid;
        int o   = idx / K;
        int kp  = idx % K;
        int q   = kp >> 8;          // 0..4
        int rem = kp & 255;
        int l   = rem >> 3;         // 0..31
        int e   = rem & 7;
        int r   = q * 8 + e;        // 0..39
        int j   = r / G;
        int g   = r % G;
        int i   = l * 8 + j;
        g_W[idx] = __float2half(coef[o * K + i * G + g] * scale[o * IN + i]);
        return;
    }

    // minmax partials: blocks PREP_BLOCKS .. PREP_BLOCKS+MM_BLOCKS-1
    const int pb = blk - PREP_BLOCKS;
    const float4* x4 = (const float4*)x;
    float lmin =  3.4e38f;
    float lmax = -3.4e38f;
    for (int i = pb * 256 + tid; i < n4; i += MM_BLOCKS * 256) {
        float4 v = x4[i];
        lmin = fminf(lmin, fminf(fminf(v.x, v.y), fminf(v.z, v.w)));
        lmax = fmaxf(lmax, fmaxf(fmaxf(v.x, v.y), fmaxf(v.z, v.w)));
    }
    #pragma unroll
    for (int off = 16; off > 0; off >>= 1) {
        lmin = fminf(lmin, __shfl_xor_sync(0xFFFFFFFFu, lmin, off));
        lmax = fmaxf(lmax, __shfl_xor_sync(0xFFFFFFFFu, lmax, off));
    }
    __shared__ float smin[8], smax[8];
    int warp = tid >> 5, lane = tid & 31;
    if (lane == 0) { smin[warp] = lmin; smax[warp] = lmax; }
    __syncthreads();
    if (warp == 0) {
        lmin = (lane < 8) ? smin[lane] :  3.4e38f;
        lmax = (lane < 8) ? smax[lane] : -3.4e38f;
        #pragma unroll
        for (int off = 4; off > 0; off >>= 1) {
            lmin = fminf(lmin, __shfl_xor_sync(0xFFFFFFFFu, lmin, off));
            lmax = fmaxf(lmax, __shfl_xor_sync(0xFFFFFFFFu, lmax, off));
        }
        if (lane == 0) { g_pmin[pb] = lmin; g_pmax[pb] = lmax; }
    }
}

// ---------------- kernel 2: basis(x) -> g_A (reduces partials inline) -------
__global__ __launch_bounds__(256)
void basis_kernel(const float* __restrict__ x, const float* __restrict__ grid) {
    __shared__ float sred[2];
    const int tid = threadIdx.x;
    const int warp = tid >> 5, lane = tid & 31;

    // reduce the 256 min/max partials (each thread one partial)
    {
        float lmin = g_pmin[tid];
        float lmax = g_pmax[tid];
        #pragma unroll
        for (int off = 16; off > 0; off >>= 1) {
            lmin = fminf(lmin, __shfl_xor_sync(0xFFFFFFFFu, lmin, off));
            lmax = fmaxf(lmax, __shfl_xor_sync(0xFFFFFFFFu, lmax, off));
        }
        __shared__ float wmin[8], wmax[8];
        if (lane == 0) { wmin[warp] = lmin; wmax[warp] = lmax; }
        __syncthreads();
        if (tid == 0) {
            float mn = wmin[0], mx = wmax[0];
            #pragma unroll
            for (int w = 1; w < 8; ++w) {
                mn = fminf(mn, wmin[w]);
                mx = fmaxf(mx, wmax[w]);
            }
            sred[0] = mn;
            sred[1] = mx;
        }
        __syncthreads();
    }
    const float xmin = sred[0];
    const float xmax = sred[1];
    const float s2 = 2.0f / (xmax - xmin + EPSF);
    const float c0 = -xmin * s2 - 1.0f;     // xn = fma(xv, s2, c0)

    const int row = blockIdx.x * 8 + warp;

    float gr[G];
    #pragma unroll
    for (int g = 0; g < G; ++g) gr[g] = __ldg(grid + g);

    const float4* xr = (const float4*)(x + (size_t)row * IN + lane * 8);
    float4 v0 = xr[0], v1 = xr[1];
    float xs[8] = {v0.x, v0.y, v0.z, v0.w, v1.x, v1.y, v1.z, v1.w};

    uint32_t hs[20];                        // 40 halves as 20 half2
    #pragma unroll
    for (int jj = 0; jj < 4; ++jj) {
        float vals[10];
        #pragma unroll
        for (int u = 0; u < 2; ++u) {
            const int j = jj * 2 + u;
            float xn = fmaf(xs[j], s2, c0);
            float bb[G];
            float bsum = EPSF;
            #pragma unroll
            for (int g = 0; g < G; ++g) {
                float s = xn - gr[g];
                float t = s * s;
                float v = fmaxf(fmaf(-t, fabsf(s), 1.0f), 0.0f);
                bb[g] = v;
                bsum += v;
            }
            float inv = 1.0f / bsum;
            #pragma unroll
            for (int g = 0; g < G; ++g) vals[u * 5 + g] = bb[g] * inv;
        }
        #pragma unroll
        for (int p = 0; p < 5; ++p) {
            __half2 h2 = __floats2half2_rn(vals[2 * p], vals[2 * p + 1]);
            hs[jj * 5 + p] = *(uint32_t*)&h2;
        }
    }
    uint4* gdst = (uint4*)(g_A + (size_t)row * K);
    #pragma unroll
    for (int q = 0; q < 5; ++q) {
        uint4 u = make_uint4(hs[4 * q], hs[4 * q + 1],
                             hs[4 * q + 2], hs[4 * q + 3]);
        gdst[q * 32 + lane] = u;
    }
}

// ---------------- kernel 3: fp16 GEMM, 8 warps of 64x64, full-OUT tiles -----
// C[b][o] = sum_k A[b][k] * W[o][k] + bias[o]
// wm = (warp>>2)*64 (2 groups), wn = (warp&3)*64 (4 groups): 128x256 covered.
__global__ __launch_bounds__(256, 1)
void kan_gemm_kernel(const float* __restrict__ bias, float* __restrict__ out) {
    extern __shared__ __align__(16) char smem_raw[];
    float* bias_s = (float*)smem_raw;              // 256 floats
    char* stg = smem_raw + 1024;                   // STAGES x 48KB

    const int tid = threadIdx.x;
    const int bm0 = blockIdx.x * BM;

    if (tid < BN) bias_s[tid] = bias[tid];

    const int warp = tid >> 5, lane = tid & 31;
    const int wm = (warp >> 2) * 64;
    const int wn = (warp & 3) * 64;

    float acc[4][8][4];
    #pragma unroll
    for (int mi = 0; mi < 4; ++mi)
        #pragma unroll
        for (int nf = 0; nf < 8; ++nf)
            #pragma unroll
            for (int q = 0; q < 4; ++q) acc[mi][nf][q] = 0.0f;

    auto load_stage = [&](int ic) {
        char* base = stg + (ic % STAGES) * STG_BYTES;
        char* ab = base;                 // A: 128 rows x 128B
        char* bb = base + BM * 128;      // B: 256 rows x 128B
        #pragma unroll
        for (int q = 0; q < 4; ++q) {    // A: 1024 chunks
            int idx = q * 256 + tid;
            int row = idx >> 3;
            int c   = idx & 7;
            cp_async16(ab + swz(row * 128 + c * 16),
                       g_A + (size_t)(bm0 + row) * K + ic * BK + c * 8);
        }
        #pragma unroll
        for (int q = 0; q < 8; ++q) {    // B: 2048 chunks
            int idx = q * 256 + tid;
            int row = idx >> 3;
            int c   = idx & 7;
            cp_async16(bb + swz(row * 128 + c * 16),
                       g_W + (size_t)row * K + ic * BK + c * 8);
        }
        CP_COMMIT();
    };

    load_stage(0);
    load_stage(1);

    for (int ic = 0; ic < NCH; ++ic) {
        if (ic == NCH - 1) { CP_WAIT(0); } else { CP_WAIT(1); }
        __syncthreads();
        // single barrier per iter: the load below targets the buffer of chunk
        // ic-1, whose MMAs every warp finished before this barrier.
        if (ic + 2 < NCH) load_stage(ic + 2);

        const char* base = stg + (ic % STAGES) * STG_BYTES;
        const char* as = base;
        const char* bs = base + BM * 128;

        #pragma unroll
        for (int ks = 0; ks < 4; ++ks) {
            const int k0 = ks * 16;
            uint32_t a[4][4];
            #pragma unroll
            for (int mi = 0; mi < 4; ++mi) {
                int row = wm + mi * 16 + (lane & 15);
                int cb  = k0 * 2 + (lane >> 4) * 16;
                uint32_t addr = (uint32_t)__cvta_generic_to_shared(
                    as + swz(row * 128 + cb));
                ldm_x4(a[mi], addr);
            }
            uint32_t b[4][4];
            #pragma unroll
            for (int ni = 0; ni < 4; ++ni) {
                int row = wn + ni * 16 + (lane & 7) + ((lane >> 4) << 3);
                int cb  = k0 * 2 + (((lane >> 3) & 1) << 4);
                uint32_t addr = (uint32_t)__cvta_generic_to_shared(
                    bs + swz(row * 128 + cb));
                ldm_x4(b[ni], addr);
            }
            #pragma unroll
            for (int mi = 0; mi < 4; ++mi)
                #pragma unroll
                for (int nf = 0; nf < 8; ++nf) {
                    const uint32_t b0 = b[nf >> 1][(nf & 1) * 2];
                    const uint32_t b1 = b[nf >> 1][(nf & 1) * 2 + 1];
                    asm volatile(
                        "mma.sync.aligned.m16n8k16.row.col.f32.f16.f16.f32 "
                        "{%0,%1,%2,%3}, {%4,%5,%6,%7}, {%8,%9}, {%0,%1,%2,%3};"
                        : "+f"(acc[mi][nf][0]), "+f"(acc[mi][nf][1]),
                          "+f"(acc[mi][nf][2]), "+f"(acc[mi][nf][3])
                        : "r"(a[mi][0]), "r"(a[mi][1]),
                          "r"(a[mi][2]), "r"(a[mi][3]),
                          "r"(b0), "r"(b1));
                }
        }
    }

    // epilogue: + bias, float2 stores
    #pragma unroll
    for (int mi = 0; mi < 4; ++mi) {
        int r = bm0 + wm + mi * 16 + (lane >> 2);
        #pragma unroll
        for (int nf = 0; nf < 8; ++nf) {
            int cl = wn + nf * 8 + ((lane & 3) << 1);
            float b0 = bias_s[cl];
            float b1 = bias_s[cl + 1];
            float2 v0 = make_float2(acc[mi][nf][0] + b0, acc[mi][nf][1] + b1);
            float2 v1 = make_float2(acc[mi][nf][2] + b0, acc[mi][nf][3] + b1);
            *(float2*)(out + (size_t)r * OUT + cl) = v0;
            *(float2*)(out + (size_t)(r + 8) * OUT + cl) = v1;
        }
    }
}

// ---------------------------------------------------------------------------
static constexpr int GEMM_SMEM = 1024 + STAGES * STG_BYTES;   // ~145KB

extern "C" void kernel_launch(void* const* d_in, const int* in_sizes, int n_in,
                              void* d_out, int out_size) {
    const float* x     = (const float*)d_in[0];
    const float* grid  = (const float*)d_in[1];
    const float* coef  = (const float*)d_in[2];
    const float* scale = (const float*)d_in[3];
    const float* bias  = (const float*)d_in[4];
    float* out = (float*)d_out;

    const int B = in_sizes[0] / IN;

    cudaFuncSetAttribute(kan_gemm_kernel,
                         cudaFuncAttributeMaxDynamicSharedMemorySize,
                         GEMM_SMEM);

    pre_kernel<<<PREP_BLOCKS + MM_BLOCKS, 256>>>(x, coef, scale,
                                                 in_sizes[0] / 4);
    basis_kernel<<<B / 8, 256>>>(x, grid);
    kan_gemm_kernel<<<B / BM, 256, GEMM_SMEM>>>(bias, out);
}

// round 13
// speedup vs baseline: 1.1621x; 1.0805x over previous
#include <cuda_runtime.h>
#include <cuda_fp16.h>
#include <cstdint>

#define EPSF 1e-8f

static constexpr int IN  = 256;
static constexpr int OUT = 256;
static constexpr int G   = 5;
static constexpr int K   = IN * G;    // 1280
static constexpr int BQ  = 32768;

// GEMM tiling: BM=128, BN=256(full OUT), 8 warps of 64x64
static constexpr int BM = 128;
static constexpr int BN = 256;
static constexpr int BK = 64;         // halves per chunk = 128B rows
static constexpr int NCH = K / BK;    // 20
static constexpr int STAGES = 3;
static constexpr int STG_BYTES = (BM + BN) * 128;   // 48KB per stage

static constexpr int PREP_BLOCKS = (OUT * K) / 256;   // 1280
static constexpr int MM_BLOCKS   = 1024;              // minmax partial blocks

// K-permutation: k' = q*256 + l*8 + e, original k = 40l + r, r = 8q + e.
// Basis lane l emits 40 halves; its q-th uint4 lands at uint4 index q*32+l
// of the row -> coalesced warp stores. W uses the same permutation.

// ---------------- device globals (scratch; no allocations allowed) ----------
__device__ float  g_pmin[MM_BLOCKS];
__device__ float  g_pmax[MM_BLOCKS];
__device__ __half g_W[OUT * K];              // coef*scale fp16, permuted k
__device__ __half g_A[(size_t)BQ * K];       // basis fp16, permuted k

__device__ __forceinline__ void cp_async16(void* smem_dst, const void* gsrc) {
    uint32_t s = (uint32_t)__cvta_generic_to_shared(smem_dst);
    asm volatile("cp.async.cg.shared.global [%0], [%1], 16;\n"
                 :: "r"(s), "l"(gsrc));
}
#define CP_COMMIT() asm volatile("cp.async.commit_group;\n" ::: "memory")
#define CP_WAIT(n)  asm volatile("cp.async.wait_group %0;\n" :: "n"(n) : "memory")

// XOR swizzle for 128-byte rows, conflict-free ldmatrix
__device__ __forceinline__ uint32_t swz(uint32_t b) {
    return b ^ ((b >> 3) & 0x70);
}

__device__ __forceinline__ void ldm_x4(uint32_t* r, uint32_t addr) {
    asm volatile(
        "ldmatrix.sync.aligned.m8n8.x4.shared.b16 {%0,%1,%2,%3}, [%4];"
        : "=r"(r[0]), "=r"(r[1]), "=r"(r[2]), "=r"(r[3]) : "r"(addr));
}

// ---------------- kernel 1: prep W (blocks 0..1279) + minmax partials -------
__global__ __launch_bounds__(256)
void pre_kernel(const float* __restrict__ x,
                const float* __restrict__ coef,
                const float* __restrict__ scale,
                int n4) {
    const int blk = blockIdx.x;
    const int tid = threadIdx.x;

    if (blk < PREP_BLOCKS) {
        int idx = blk * 256 + tid;
        int o   = idx / K;
        int kp  = idx % K;
        int q   = kp >> 8;          // 0..4
        int rem = kp & 255;
        int l   = rem >> 3;         // 0..31
        int e   = rem & 7;
        int r   = q * 8 + e;        // 0..39
        int j   = r / G;
        int g   = r % G;
        int i   = l * 8 + j;
        g_W[idx] = __float2half(coef[o * K + i * G + g] * scale[o * IN + i]);
        return;
    }

    // minmax partials: blocks PREP_BLOCKS .. PREP_BLOCKS+MM_BLOCKS-1
    const int pb = blk - PREP_BLOCKS;
    const float4* x4 = (const float4*)x;
    float lmin =  3.4e38f;
    float lmax = -3.4e38f;
    for (int i = pb * 256 + tid; i < n4; i += MM_BLOCKS * 256) {
        float4 v = x4[i];
        lmin = fminf(lmin, fminf(fminf(v.x, v.y), fminf(v.z, v.w)));
        lmax = fmaxf(lmax, fmaxf(fmaxf(v.x, v.y), fmaxf(v.z, v.w)));
    }
    #pragma unroll
    for (int off = 16; off > 0; off >>= 1) {
        lmin = fminf(lmin, __shfl_xor_sync(0xFFFFFFFFu, lmin, off));
        lmax = fmaxf(lmax, __shfl_xor_sync(0xFFFFFFFFu, lmax, off));
    }
    __shared__ float smin[8], smax[8];
    int warp = tid >> 5, lane = tid & 31;
    if (lane == 0) { smin[warp] = lmin; smax[warp] = lmax; }
    __syncthreads();
    if (warp == 0) {
        lmin = (lane < 8) ? smin[lane] :  3.4e38f;
        lmax = (lane < 8) ? smax[lane] : -3.4e38f;
        #pragma unroll
        for (int off = 4; off > 0; off >>= 1) {
            lmin = fminf(lmin, __shfl_xor_sync(0xFFFFFFFFu, lmin, off));
            lmax = fmaxf(lmax, __shfl_xor_sync(0xFFFFFFFFu, lmax, off));
        }
        if (lane == 0) { g_pmin[pb] = lmin; g_pmax[pb] = lmax; }
    }
}

// ---------------- kernel 2: basis(x) -> g_A (reduces partials inline) -------
__global__ __launch_bounds__(256)
void basis_kernel(const float* __restrict__ x, const float* __restrict__ grid) {
    __shared__ float sred[2];
    const int tid = threadIdx.x;
    const int warp = tid >> 5, lane = tid & 31;

    // reduce the MM_BLOCKS min/max partials
    {
        float lmin =  3.4e38f;
        float lmax = -3.4e38f;
        #pragma unroll
        for (int p = 0; p < MM_BLOCKS / 256; ++p) {
            lmin = fminf(lmin, g_pmin[p * 256 + tid]);
            lmax = fmaxf(lmax, g_pmax[p * 256 + tid]);
        }
        #pragma unroll
        for (int off = 16; off > 0; off >>= 1) {
            lmin = fminf(lmin, __shfl_xor_sync(0xFFFFFFFFu, lmin, off));
            lmax = fmaxf(lmax, __shfl_xor_sync(0xFFFFFFFFu, lmax, off));
        }
        __shared__ float wmin[8], wmax[8];
        if (lane == 0) { wmin[warp] = lmin; wmax[warp] = lmax; }
        __syncthreads();
        if (tid == 0) {
            float mn = wmin[0], mx = wmax[0];
            #pragma unroll
            for (int w = 1; w < 8; ++w) {
                mn = fminf(mn, wmin[w]);
                mx = fmaxf(mx, wmax[w]);
            }
            sred[0] = mn;
            sred[1] = mx;
        }
        __syncthreads();
    }
    const float xmin = sred[0];
    const float xmax = sred[1];
    const float s2 = 2.0f / (xmax - xmin + EPSF);
    const float c0 = -xmin * s2 - 1.0f;     // xn = fma(xv, s2, c0)

    const int row = blockIdx.x * 8 + warp;

    float gr[G];
    #pragma unroll
    for (int g = 0; g < G; ++g) gr[g] = __ldg(grid + g);

    const float4* xr = (const float4*)(x + (size_t)row * IN + lane * 8);
    float4 v0 = xr[0], v1 = xr[1];
    float xs[8] = {v0.x, v0.y, v0.z, v0.w, v1.x, v1.y, v1.z, v1.w};

    uint32_t hs[20];                        // 40 halves as 20 half2
    #pragma unroll
    for (int jj = 0; jj < 4; ++jj) {
        float vals[10];
        #pragma unroll
        for (int u = 0; u < 2; ++u) {
            const int j = jj * 2 + u;
            float xn = fmaf(xs[j], s2, c0);
            float bb[G];
            float bsum = EPSF;
            #pragma unroll
            for (int g = 0; g < G; ++g) {
                float s = xn - gr[g];
                float t = s * s;
                float v = fmaxf(fmaf(-t, fabsf(s), 1.0f), 0.0f);
                bb[g] = v;
                bsum += v;
            }
            float inv = 1.0f / bsum;
            #pragma unroll
            for (int g = 0; g < G; ++g) vals[u * 5 + g] = bb[g] * inv;
        }
        #pragma unroll
        for (int p = 0; p < 5; ++p) {
            __half2 h2 = __floats2half2_rn(vals[2 * p], vals[2 * p + 1]);
            hs[jj * 5 + p] = *(uint32_t*)&h2;
        }
    }
    uint4* gdst = (uint4*)(g_A + (size_t)row * K);
    #pragma unroll
    for (int q = 0; q < 5; ++q) {
        uint4 u = make_uint4(hs[4 * q], hs[4 * q + 1],
                             hs[4 * q + 2], hs[4 * q + 3]);
        gdst[q * 32 + lane] = u;
    }
}

// ---------------- kernel 3: fp16 GEMM, 64x64 warps, reg-double-buffered -----
// C[b][o] = sum_k A[b][k] * W[o][k] + bias[o]
// wm = (warp>>2)*64 (2 groups), wn = (warp&3)*64 (4 groups): 128x256 covered.
__global__ __launch_bounds__(256, 1)
void kan_gemm_kernel(const float* __restrict__ bias, float* __restrict__ out) {
    extern __shared__ __align__(16) char smem_raw[];
    float* bias_s = (float*)smem_raw;              // 256 floats
    char* stg = smem_raw + 1024;                   // STAGES x 48KB

    const int tid = threadIdx.x;
    const int bm0 = blockIdx.x * BM;

    if (tid < BN) bias_s[tid] = bias[tid];

    const int warp = tid >> 5, lane = tid & 31;
    const int wm = (warp >> 2) * 64;
    const int wn = (warp & 3) * 64;

    // swizzled tile-relative base offsets (kstep 0); kstep ks adds byte col 32*ks
    uint32_t aoff[4], boff[4];
    #pragma unroll
    for (int mi = 0; mi < 4; ++mi) {
        int row = wm + mi * 16 + (lane & 15);
        aoff[mi] = row * 128 + ((lane >> 4) * 16);
    }
    #pragma unroll
    for (int ni = 0; ni < 4; ++ni) {
        int row = wn + ni * 16 + (lane & 7) + ((lane >> 4) << 3);
        boff[ni] = row * 128 + (((lane >> 3) & 1) << 4);
    }

    float acc[4][8][4];
    #pragma unroll
    for (int mi = 0; mi < 4; ++mi)
        #pragma unroll
        for (int nf = 0; nf < 8; ++nf)
            #pragma unroll
            for (int q = 0; q < 4; ++q) acc[mi][nf][q] = 0.0f;

    auto load_stage = [&](int ic) {
        char* base = stg + (ic % STAGES) * STG_BYTES;
        char* ab = base;                 // A: 128 rows x 128B
        char* bb = base + BM * 128;      // B: 256 rows x 128B
        #pragma unroll
        for (int q = 0; q < 4; ++q) {    // A: 1024 chunks
            int idx = q * 256 + tid;
            int row = idx >> 3;
            int c   = idx & 7;
            cp_async16(ab + swz(row * 128 + c * 16),
                       g_A + (size_t)(bm0 + row) * K + ic * BK + c * 8);
        }
        #pragma unroll
        for (int q = 0; q < 8; ++q) {    // B: 2048 chunks
            int idx = q * 256 + tid;
            int row = idx >> 3;
            int c   = idx & 7;
            cp_async16(bb + swz(row * 128 + c * 16),
                       g_W + (size_t)row * K + ic * BK + c * 8);
        }
        CP_COMMIT();
    };

    uint32_t afr[2][4][4], bfr[2][4][4];

    auto frag_load = [&](int ic, int ks, int buf) {
        const uint32_t sb = (uint32_t)__cvta_generic_to_shared(
            stg + (ic % STAGES) * STG_BYTES);
        const uint32_t ab = sb;
        const uint32_t bb = sb + BM * 128;
        const uint32_t kc = (uint32_t)(ks * 32);
        #pragma unroll
        for (int mi = 0; mi < 4; ++mi)
            ldm_x4(afr[buf][mi], ab + swz(aoff[mi] + kc));
        #pragma unroll
        for (int ni = 0; ni < 4; ++ni)
            ldm_x4(bfr[buf][ni], bb + swz(boff[ni] + kc));
    };

    auto mma_step = [&](int buf) {
        #pragma unroll
        for (int mi = 0; mi < 4; ++mi)
            #pragma unroll
            for (int nf = 0; nf < 8; ++nf) {
                const uint32_t b0 = bfr[buf][nf >> 1][(nf & 1) * 2];
                const uint32_t b1 = bfr[buf][nf >> 1][(nf & 1) * 2 + 1];
                asm volatile(
                    "mma.sync.aligned.m16n8k16.row.col.f32.f16.f16.f32 "
                    "{%0,%1,%2,%3}, {%4,%5,%6,%7}, {%8,%9}, {%0,%1,%2,%3};"
                    : "+f"(acc[mi][nf][0]), "+f"(acc[mi][nf][1]),
                      "+f"(acc[mi][nf][2]), "+f"(acc[mi][nf][3])
                    : "r"(afr[buf][mi][0]), "r"(afr[buf][mi][1]),
                      "r"(afr[buf][mi][2]), "r"(afr[buf][mi][3]),
                      "r"(b0), "r"(b1));
            }
    };

    load_stage(0);
    load_stage(1);
    CP_WAIT(1);
    __syncthreads();
    frag_load(0, 0, 0);

    int cur = 0;
    for (int ic = 0; ic < NCH; ++ic) {
        if (ic + 2 < NCH) load_stage(ic + 2);
        #pragma unroll
        for (int ks = 0; ks < 4; ++ks) {
            const int nxt = cur ^ 1;
            if (ks < 3) {
                frag_load(ic, ks + 1, nxt);
            } else if (ic + 1 < NCH) {
                if (ic == NCH - 2) { CP_WAIT(0); } else { CP_WAIT(1); }
                __syncthreads();
                frag_load(ic + 1, 0, nxt);
            }
            mma_step(cur);
            cur = nxt;
        }
    }

    // epilogue: + bias, float2 stores
    #pragma unroll
    for (int mi = 0; mi < 4; ++mi) {
        int r = bm0 + wm + mi * 16 + (lane >> 2);
        #pragma unroll
        for (int nf = 0; nf < 8; ++nf) {
            int cl = wn + nf * 8 + ((lane & 3) << 1);
            float b0 = bias_s[cl];
            float b1 = bias_s[cl + 1];
            float2 v0 = make_float2(acc[mi][nf][0] + b0, acc[mi][nf][1] + b1);
            float2 v1 = make_float2(acc[mi][nf][2] + b0, acc[mi][nf][3] + b1);
            *(float2*)(out + (size_t)r * OUT + cl) = v0;
            *(float2*)(out + (size_t)(r + 8) * OUT + cl) = v1;
        }
    }
}

// ---------------------------------------------------------------------------
static constexpr int GEMM_SMEM = 1024 + STAGES * STG_BYTES;   // ~145KB

extern "C" void kernel_launch(void* const* d_in, const int* in_sizes, int n_in,
                              void* d_out, int out_size) {
    const float* x     = (const float*)d_in[0];
    const float* grid  = (const float*)d_in[1];
    const float* coef  = (const float*)d_in[2];
    const float* scale = (const float*)d_in[3];
    const float* bias  = (const float*)d_in[4];
    float* out = (float*)d_out;

    const int B = in_sizes[0] / IN;

    cudaFuncSetAttribute(kan_gemm_kernel,
                         cudaFuncAttributeMaxDynamicSharedMemorySize,
                         GEMM_SMEM);

    pre_kernel<<<PREP_BLOCKS + MM_BLOCKS, 256>>>(x, coef, scale,
                                                 in_sizes[0] / 4);
    basis_kernel<<<B / 8, 256>>>(x, grid);
    kan_gemm_kernel<<<B / BM, 256, GEMM_SMEM>>>(bias, out);
}